// round 8
// baseline (speedup 1.0000x reference)
#include <cuda_runtime.h>
#include <cuda_fp16.h>
#include <cstdint>

#define TOK 512
#define HD  4096
#define MDIM 11008

// ---------------- static scratch (allocation-free rule) ----------------
static __device__ __half g_xh[TOK * HD];        // x in fp16
static __device__ __half g_g [TOK * MDIM];      // gate GEMM output (fp16)
static __device__ __half g_h [TOK * MDIM];      // h = silu(g)*u (fp16)

__constant__ float c_nf4[16] = {
    -1.0f, -0.6961928009986877f, -0.5250730514526367f, -0.39491748809814453f,
    -0.28444138169288635f, -0.18477343022823334f, -0.09105003625154495f, 0.0f,
    0.07958029955625534f, 0.16093020141124725f, 0.24611230194568634f,
    0.33791524171829224f, 0.44070982933044434f, 0.5626170039176941f,
    0.7229568362236023f, 1.0f};

// ---------------- helpers ----------------
__device__ __forceinline__ void cp_async16(void* smem, const void* gmem) {
    uint32_t s = (uint32_t)__cvta_generic_to_shared(smem);
    asm volatile("cp.async.cg.shared.global [%0], [%1], 16;\n" :: "r"(s), "l"(gmem));
}
__device__ __forceinline__ void cp_commit() {
    asm volatile("cp.async.commit_group;\n" ::: "memory");
}
template <int N>
__device__ __forceinline__ void cp_wait() {
    asm volatile("cp.async.wait_group %0;\n" :: "n"(N) : "memory");
}
__device__ __forceinline__ void ldsm4(uint32_t (&r)[4], const __half* p) {
    uint32_t s = (uint32_t)__cvta_generic_to_shared((void*)p);
    asm volatile("ldmatrix.sync.aligned.m8n8.x4.shared.b16 {%0,%1,%2,%3}, [%4];\n"
                 : "=r"(r[0]), "=r"(r[1]), "=r"(r[2]), "=r"(r[3]) : "r"(s));
}
__device__ __forceinline__ void mma16816(float (&d)[4], const uint32_t (&a)[4],
                                         uint32_t b0, uint32_t b1) {
    asm volatile(
        "mma.sync.aligned.m16n8k16.row.col.f32.f16.f16.f32 "
        "{%0,%1,%2,%3},{%4,%5,%6,%7},{%8,%9},{%0,%1,%2,%3};\n"
        : "+f"(d[0]), "+f"(d[1]), "+f"(d[2]), "+f"(d[3])
        : "r"(a[0]), "r"(a[1]), "r"(a[2]), "r"(a[3]), "r"(b0), "r"(b1));
}
__device__ __forceinline__ float siluf(float v) {
    return v / (1.0f + __expf(-v));
}

// ---------------- kernel: x fp32 -> fp16 ----------------
__global__ void cvt_x_kernel(const float* __restrict__ x, __half* __restrict__ xh) {
    int i = blockIdx.x * blockDim.x + threadIdx.x;   // handles 4 elements
    float4 v = ((const float4*)x)[i];
    ((__half2*)xh)[2 * i]     = __floats2half2_rn(v.x, v.y);
    ((__half2*)xh)[2 * i + 1] = __floats2half2_rn(v.z, v.w);
}

// ---------------- fused NF4-dequant GEMM ----------------
// C[M=tok, N] = A[tok,K](fp16) * dequant(Bcodes[N,K])^T
// Block tile 128x128x32, 2-stage double buffer, 8 warps (2m x 4n), warp 64x32.
// B path: LDG int4 codes (tile kt+1) -> regs, NF4 smem-table lookup * absmax,
// STS fp16 into sB[other stage]. A path: cp.async fp16.
// EPI 0: store fp16 to G.
// EPI 1: load G fp16, h = silu(G)*acc, store fp16 to H.
// EPI 2: store fp32 to Out.
#define BM 128
#define BN 128
#define BK 32
#define LDS_W 40   // 32 + 8 halfs padding

template <int EPI>
__global__ __launch_bounds__(256, 2)
void gemm_dq(const __half* __restrict__ A, const int* __restrict__ Bc,
             const float* __restrict__ Bam, int K, int N,
             __half* __restrict__ G, const __half* __restrict__ Gin,
             __half* __restrict__ H, float* __restrict__ Fout) {
    __shared__ __half sA[2][BM * LDS_W];
    __shared__ __half sB[2][BN * LDS_W];
    __shared__ float tab[16];

    const int tid  = threadIdx.x;
    const int lane = tid & 31;
    const int warp = tid >> 5;
    const int wm   = warp >> 2;     // 0..1
    const int wn   = warp & 3;      // 0..3
    const int bm   = blockIdx.x;    // token tile (fast dim -> L2 dedup of B)
    const int bn   = blockIdx.y;    // weight tile

    const size_t rowA0 = (size_t)bm * BM;
    const size_t rowB0 = (size_t)bn * BN;

    if (tid < 16) tab[tid] = c_nf4[tid];

    // ---- B code chunk mapping: 4 chunks/thread, chunk = (row, 4 k-codes) ----
    // ch = tid + i*256 : r = ch>>3 (0..127), c = ch&7 (k-offset c*4 within BK)
    const int* bp[4];
    const float* ap[4];
    int sdst[4];
#pragma unroll
    for (int i = 0; i < 4; ++i) {
        int ch = tid + i * 256;
        int r = ch >> 3, c = ch & 7;
        bp[i]   = Bc + (size_t)(rowB0 + r) * K + c * 4;
        ap[i]   = Bam + (size_t)(rowB0 + r) * (K >> 6);
        sdst[i] = r * LDS_W + c * 4;
    }

    // A tile loader (cp.async): 512 chunks of 16B, 2/thread
    auto loadA = [&](int st, int k0) {
#pragma unroll
        for (int i = 0; i < 2; ++i) {
            int ch = tid + i * 256;
            int r = ch >> 2, cc = (ch & 3) * 8;
            cp_async16(&sA[st][r * LDS_W + cc], A + (rowA0 + r) * K + k0 + cc);
        }
    };

    int4  creg[4];
    float amreg[4];
    auto ldgB = [&](int kt) {
#pragma unroll
        for (int i = 0; i < 4; ++i) {
            creg[i]  = *(const int4*)(bp[i] + kt * BK);
            amreg[i] = __ldg(ap[i] + (kt >> 1));
        }
    };
    auto cvtB = [&](int st) {
#pragma unroll
        for (int i = 0; i < 4; ++i) {
            float am = amreg[i];
            __half2 h0 = __floats2half2_rn(tab[creg[i].x] * am, tab[creg[i].y] * am);
            __half2 h1 = __floats2half2_rn(tab[creg[i].z] * am, tab[creg[i].w] * am);
            __half2* d = (__half2*)&sB[st][sdst[i]];
            uint2 v = make_uint2(*(uint32_t*)&h0, *(uint32_t*)&h1);
            *(uint2*)d = v;
        }
    };

    float acc[4][4][4] = {};

    // prologue: tile 0
    ldgB(0);
    loadA(0, 0);
    cp_commit();
    __syncthreads();          // tab ready
    cvtB(0);

    const int KT = K / BK;
    for (int kt = 0; kt < KT; ++kt) {
        const int rs = kt & 1;
        if (kt + 1 < KT) {
            ldgB(kt + 1);
            loadA(rs ^ 1, (kt + 1) * BK);
            cp_commit();
            cp_wait<1>();
        } else {
            cp_wait<0>();
        }
        __syncthreads();      // sA[rs] + sB[rs] visible to all

        const __half* a_s = sA[rs];
        const __half* b_s = sB[rs];
#pragma unroll
        for (int kk = 0; kk < 2; ++kk) {
            uint32_t af[4][4], bf[2][4];
            int arow = wm * 64 + (lane & 15);
            int acol = kk * 16 + (lane >> 4) * 8;
#pragma unroll
            for (int mi = 0; mi < 4; ++mi)
                ldsm4(af[mi], a_s + (arow + mi * 16) * LDS_W + acol);
            int brow = wn * 32 + (lane & 7) + ((lane >> 4) << 3);
            int bcol = kk * 16 + ((lane >> 3) & 1) * 8;
#pragma unroll
            for (int nb = 0; nb < 2; ++nb)
                ldsm4(bf[nb], b_s + (brow + nb * 16) * LDS_W + bcol);
#pragma unroll
            for (int mi = 0; mi < 4; ++mi)
#pragma unroll
                for (int ni = 0; ni < 4; ++ni)
                    mma16816(acc[mi][ni], af[mi],
                             bf[ni >> 1][(ni & 1) * 2], bf[ni >> 1][(ni & 1) * 2 + 1]);
        }
        if (kt + 1 < KT) cvtB(rs ^ 1);   // fill other stage for next iter
        __syncthreads();      // compute+STS done before next overwrite
    }

    // epilogue
    const int m0 = bm * BM + wm * 64;
    const int n0 = bn * BN + wn * 32;
#pragma unroll
    for (int mi = 0; mi < 4; ++mi) {
#pragma unroll
        for (int ni = 0; ni < 4; ++ni) {
            int r = m0 + mi * 16 + (lane >> 2);
            int c = n0 + ni * 8 + (lane & 3) * 2;
            float* p = acc[mi][ni];
            if (EPI == 0) {
                *(__half2*)(G + (size_t)r * N + c) = __floats2half2_rn(p[0], p[1]);
                *(__half2*)(G + (size_t)(r + 8) * N + c) = __floats2half2_rn(p[2], p[3]);
            } else if (EPI == 1) {
                __half2 gv0 = *(const __half2*)(Gin + (size_t)r * N + c);
                __half2 gv1 = *(const __half2*)(Gin + (size_t)(r + 8) * N + c);
                float2 g0 = __half22float2(gv0);
                float2 g1 = __half22float2(gv1);
                *(__half2*)(H + (size_t)r * N + c) =
                    __floats2half2_rn(siluf(g0.x) * p[0], siluf(g0.y) * p[1]);
                *(__half2*)(H + (size_t)(r + 8) * N + c) =
                    __floats2half2_rn(siluf(g1.x) * p[2], siluf(g1.y) * p[3]);
            } else {
                *(float2*)(Fout + (size_t)r * N + c)       = make_float2(p[0], p[1]);
                *(float2*)(Fout + (size_t)(r + 8) * N + c) = make_float2(p[2], p[3]);
            }
        }
    }
}

// ---------------- launch ----------------
extern "C" void kernel_launch(void* const* d_in, const int* in_sizes, int n_in,
                              void* d_out, int out_size) {
    const float* x  = (const float*)d_in[0];
    const int*   gc = (const int*)d_in[1];
    const float* ga = (const float*)d_in[2];
    const int*   uc = (const int*)d_in[3];
    const float* ua = (const float*)d_in[4];
    const int*   dc = (const int*)d_in[5];
    const float* da = (const float*)d_in[6];
    float* out = (float*)d_out;

    __half *xh, *gg, *hh;
    cudaGetSymbolAddress((void**)&xh, g_xh);
    cudaGetSymbolAddress((void**)&gg, g_g);
    cudaGetSymbolAddress((void**)&hh, g_h);

    cvt_x_kernel<<<(TOK * HD / 4) / 256, 256>>>(x, xh);

    dim3 g12(TOK / BM, MDIM / BN);   // (4, 86)
    gemm_dq<0><<<g12, 256>>>(xh, gc, ga, HD, MDIM, gg, nullptr, nullptr, nullptr);
    gemm_dq<1><<<g12, 256>>>(xh, uc, ua, HD, MDIM, nullptr, gg, hh, nullptr);

    dim3 g3(TOK / BM, HD / BN);      // (4, 32)
    gemm_dq<2><<<g3, 256>>>(hh, dc, da, MDIM, HD, nullptr, nullptr, nullptr, out);
}

// round 12
// speedup vs baseline: 1.2652x; 1.2652x over previous
#include <cuda_runtime.h>
#include <cuda_fp16.h>
#include <cstdint>

#define TOK 512
#define HD  4096
#define MDIM 11008

// ---------------- static scratch (allocation-free rule) ----------------
static __device__ __half g_xh[TOK * HD];        // x in fp16
static __device__ __half g_g [TOK * MDIM];      // gate GEMM output (fp16)
static __device__ __half g_h [TOK * MDIM];      // h = silu(g)*u (fp16)

__constant__ float c_nf4[16] = {
    -1.0f, -0.6961928009986877f, -0.5250730514526367f, -0.39491748809814453f,
    -0.28444138169288635f, -0.18477343022823334f, -0.09105003625154495f, 0.0f,
    0.07958029955625534f, 0.16093020141124725f, 0.24611230194568634f,
    0.33791524171829224f, 0.44070982933044434f, 0.5626170039176941f,
    0.7229568362236023f, 1.0f};

// ---------------- helpers ----------------
__device__ __forceinline__ void cp_async16(void* smem, const void* gmem) {
    uint32_t s = (uint32_t)__cvta_generic_to_shared(smem);
    asm volatile("cp.async.cg.shared.global [%0], [%1], 16;\n" :: "r"(s), "l"(gmem));
}
__device__ __forceinline__ void cp_commit() {
    asm volatile("cp.async.commit_group;\n" ::: "memory");
}
template <int N>
__device__ __forceinline__ void cp_wait() {
    asm volatile("cp.async.wait_group %0;\n" :: "n"(N) : "memory");
}
__device__ __forceinline__ void ldsm4(uint32_t (&r)[4], const __half* p) {
    uint32_t s = (uint32_t)__cvta_generic_to_shared((void*)p);
    asm volatile("ldmatrix.sync.aligned.m8n8.x4.shared.b16 {%0,%1,%2,%3}, [%4];\n"
                 : "=r"(r[0]), "=r"(r[1]), "=r"(r[2]), "=r"(r[3]) : "r"(s));
}
__device__ __forceinline__ void mma16816(float (&d)[4], const uint32_t (&a)[4],
                                         uint32_t b0, uint32_t b1) {
    asm volatile(
        "mma.sync.aligned.m16n8k16.row.col.f32.f16.f16.f32 "
        "{%0,%1,%2,%3},{%4,%5,%6,%7},{%8,%9},{%0,%1,%2,%3};\n"
        : "+f"(d[0]), "+f"(d[1]), "+f"(d[2]), "+f"(d[3])
        : "r"(a[0]), "r"(a[1]), "r"(a[2]), "r"(a[3]), "r"(b0), "r"(b1));
}
__device__ __forceinline__ float siluf(float v) {
    return v / (1.0f + __expf(-v));
}

// ---------------- kernel: x fp32 -> fp16 ----------------
__global__ void cvt_x_kernel(const float* __restrict__ x, __half* __restrict__ xh) {
    int i = blockIdx.x * blockDim.x + threadIdx.x;   // handles 4 elements
    float4 v = ((const float4*)x)[i];
    ((__half2*)xh)[2 * i]     = __floats2half2_rn(v.x, v.y);
    ((__half2*)xh)[2 * i + 1] = __floats2half2_rn(v.z, v.w);
}

// ---------------- fused NF4-dequant GEMM ----------------
// C[M=tok, N] = A[tok,K](fp16) * dequant(Bcodes[N,K])^T
// Block tile 64x128x64, 2-stage double buffer, ONE sync per kt.
// 8 warps (2m x 4n), warp tile 32x32. 2 CTAs/SM co-residency.
// B path: LDG int4 codes (tile kt+1) -> regs; after MMA block, NF4 table
// lookup * absmax -> STS fp16 into sB[other stage].
// EPI 0: fp16 -> G.  EPI 1: h = silu(G)*acc -> fp16 H.  EPI 2: fp32 -> Out.
#define BM 64
#define BN 128
#define BK 64
#define LDS_W 72            // 64 + 8 halfs pad; 144B row stride (16B aligned)
#define A_ST (BM * LDS_W)   // 4608 halfs / stage
#define B_ST (BN * LDS_W)   // 9216 halfs / stage
#define SMEM_BYTES ((2 * A_ST + 2 * B_ST) * 2)   // 55296

template <int EPI>
__global__ __launch_bounds__(256, 2)
void gemm_dq(const __half* __restrict__ A, const int* __restrict__ Bc,
             const float* __restrict__ Bam, int K, int N,
             __half* __restrict__ G, const __half* __restrict__ Gin,
             __half* __restrict__ H, float* __restrict__ Fout) {
    extern __shared__ __half smdyn[];
    __half* sA = smdyn;                 // 2 stages
    __half* sB = smdyn + 2 * A_ST;      // 2 stages
    __shared__ float tab[16];

    const int tid  = threadIdx.x;
    const int lane = tid & 31;
    const int warp = tid >> 5;
    const int wm   = warp >> 2;     // 0..1
    const int wn   = warp & 3;      // 0..3
    const int bm   = blockIdx.x;    // token tile (fast dim -> L2 dedup of B)
    const int bn   = blockIdx.y;    // weight tile

    const size_t rowA0 = (size_t)bm * BM;
    const size_t rowB0 = (size_t)bn * BN;
    const int nblk = K >> 6;        // absmax blocks per row (BLOCK==BK==64)

    if (tid < 16) tab[tid] = c_nf4[tid];

    // ---- B code mapping: 8 int4 chunks/thread ----
    // chunk i: row = (tid>>4) + i*16 (0..127), code col c0 = (tid&15)*4
    const int r0 = tid >> 4;
    const int c0 = (tid & 15) * 4;
    const int*   bbase  = Bc  + (size_t)(rowB0 + r0) * K + c0;
    const float* ambase = Bam + (size_t)(rowB0 + r0) * nblk;
    const int    sdst0  = r0 * LDS_W + c0;

    // ---- A tile loader: 64x64 fp16 = 512 x 16B chunks, 2/thread ----
    auto loadA = [&](int st, int k0) {
#pragma unroll
        for (int i = 0; i < 2; ++i) {
            int ch = tid + i * 256;
            int r = ch >> 3, cc = (ch & 7) * 8;
            cp_async16(&sA[st * A_ST + r * LDS_W + cc],
                       A + (rowA0 + r) * K + k0 + cc);
        }
    };

    int4  creg[8];
    float amreg[8];
    auto ldgB = [&](int kt) {
#pragma unroll
        for (int i = 0; i < 8; ++i) {
            creg[i]  = *(const int4*)(bbase + (size_t)i * 16 * K + kt * BK);
            amreg[i] = __ldg(ambase + (size_t)i * 16 * nblk + kt);
        }
    };
    auto cvtB = [&](int st) {
        __half* dst = sB + st * B_ST;
#pragma unroll
        for (int i = 0; i < 8; ++i) {
            float am = amreg[i];
            __half2 h0 = __floats2half2_rn(tab[creg[i].x] * am, tab[creg[i].y] * am);
            __half2 h1 = __floats2half2_rn(tab[creg[i].z] * am, tab[creg[i].w] * am);
            uint2 v = make_uint2(*(uint32_t*)&h0, *(uint32_t*)&h1);
            *(uint2*)&dst[sdst0 + i * 16 * LDS_W] = v;
        }
    };

    float acc[2][4][4] = {};

    // prologue: tile 0 into stage 0
    ldgB(0);
    loadA(0, 0);
    cp_commit();
    __syncthreads();          // tab visible
    cvtB(0);

    const int KT = K / BK;
    for (int kt = 0; kt < KT; ++kt) {
        const int rs = kt & 1;
        if (kt + 1 < KT) {
            ldgB(kt + 1);                 // codes for next stage -> regs
            loadA(rs ^ 1, (kt + 1) * BK); // A for next stage -> smem
            cp_commit();
            cp_wait<1>();                 // A of current stage done
        } else {
            cp_wait<0>();
        }
        __syncthreads();   // publish current stage (A cp.async + prev cvtB STS)

        const __half* a_s = sA + rs * A_ST;
        const __half* b_s = sB + rs * B_ST;
#pragma unroll
        for (int ks = 0; ks < 4; ++ks) {
            uint32_t af[2][4], bf[2][4];
            int arow = wm * 32 + (lane & 15);
            int acol = ks * 16 + (lane >> 4) * 8;
#pragma unroll
            for (int mi = 0; mi < 2; ++mi)
                ldsm4(af[mi], a_s + (arow + mi * 16) * LDS_W + acol);
            int brow = wn * 32 + (lane & 7) + ((lane >> 4) << 3);
            int bcol = ks * 16 + ((lane >> 3) & 1) * 8;
#pragma unroll
            for (int nb = 0; nb < 2; ++nb)
                ldsm4(bf[nb], b_s + (brow + nb * 16) * LDS_W + bcol);
#pragma unroll
            for (int mi = 0; mi < 2; ++mi)
#pragma unroll
                for (int ni = 0; ni < 4; ++ni)
                    mma16816(acc[mi][ni], af[mi],
                             bf[ni >> 1][(ni & 1) * 2], bf[ni >> 1][(ni & 1) * 2 + 1]);
        }
        if (kt + 1 < KT) cvtB(rs ^ 1);   // dequant next stage (writes other buffer)
        // NOTE: no second sync — next iteration's top sync provides the hazard
        // barrier between these STS writes and their ldmatrix readers.
    }

    // epilogue
    const int m0 = bm * BM + wm * 32;
    const int n0 = bn * BN + wn * 32;
#pragma unroll
    for (int mi = 0; mi < 2; ++mi) {
#pragma unroll
        for (int ni = 0; ni < 4; ++ni) {
            int r = m0 + mi * 16 + (lane >> 2);
            int c = n0 + ni * 8 + (lane & 3) * 2;
            float* p = acc[mi][ni];
            if (EPI == 0) {
                *(__half2*)(G + (size_t)r * N + c)       = __floats2half2_rn(p[0], p[1]);
                *(__half2*)(G + (size_t)(r + 8) * N + c) = __floats2half2_rn(p[2], p[3]);
            } else if (EPI == 1) {
                __half2 gv0 = *(const __half2*)(Gin + (size_t)r * N + c);
                __half2 gv1 = *(const __half2*)(Gin + (size_t)(r + 8) * N + c);
                float2 g0 = __half22float2(gv0);
                float2 g1 = __half22float2(gv1);
                *(__half2*)(H + (size_t)r * N + c) =
                    __floats2half2_rn(siluf(g0.x) * p[0], siluf(g0.y) * p[1]);
                *(__half2*)(H + (size_t)(r + 8) * N + c) =
                    __floats2half2_rn(siluf(g1.x) * p[2], siluf(g1.y) * p[3]);
            } else {
                *(float2*)(Fout + (size_t)r * N + c)       = make_float2(p[0], p[1]);
                *(float2*)(Fout + (size_t)(r + 8) * N + c) = make_float2(p[2], p[3]);
            }
        }
    }
}

// ---------------- launch ----------------
extern "C" void kernel_launch(void* const* d_in, const int* in_sizes, int n_in,
                              void* d_out, int out_size) {
    const float* x  = (const float*)d_in[0];
    const int*   gc = (const int*)d_in[1];
    const float* ga = (const float*)d_in[2];
    const int*   uc = (const int*)d_in[3];
    const float* ua = (const float*)d_in[4];
    const int*   dc = (const int*)d_in[5];
    const float* da = (const float*)d_in[6];
    float* out = (float*)d_out;

    __half *xh, *gg, *hh;
    cudaGetSymbolAddress((void**)&xh, g_xh);
    cudaGetSymbolAddress((void**)&gg, g_g);
    cudaGetSymbolAddress((void**)&hh, g_h);

    cudaFuncSetAttribute(gemm_dq<0>, cudaFuncAttributeMaxDynamicSharedMemorySize, SMEM_BYTES);
    cudaFuncSetAttribute(gemm_dq<1>, cudaFuncAttributeMaxDynamicSharedMemorySize, SMEM_BYTES);
    cudaFuncSetAttribute(gemm_dq<2>, cudaFuncAttributeMaxDynamicSharedMemorySize, SMEM_BYTES);

    cvt_x_kernel<<<(TOK * HD / 4) / 256, 256>>>(x, xh);

    dim3 g12(TOK / BM, MDIM / BN);   // (8, 86)
    gemm_dq<0><<<g12, 256, SMEM_BYTES>>>(xh, gc, ga, HD, MDIM, gg, nullptr, nullptr, nullptr);
    gemm_dq<1><<<g12, 256, SMEM_BYTES>>>(xh, uc, ua, HD, MDIM, nullptr, gg, hh, nullptr);

    dim3 g3(TOK / BM, HD / BN);      // (8, 32)
    gemm_dq<2><<<g3, 256, SMEM_BYTES>>>(hh, dc, da, MDIM, HD, nullptr, nullptr, nullptr, out);
}